// round 3
// baseline (speedup 1.0000x reference)
#include <cuda_runtime.h>

// Problem constants
#define BSZ   2
#define TLEN  2048
#define CDIM  1024
#define NH    16
#define HD    64
#define SCALE 0.125f   // 1/sqrt(64)

// Scratch (allocation-free rule: __device__ globals)
static __device__ float g_q[BSZ * NH * TLEN * HD];   // [B,H,T,D]
static __device__ float g_k[BSZ * NH * TLEN * HD];
static __device__ float g_v[BSZ * NH * TLEN * HD];
static __device__ float g_y[BSZ * TLEN * CDIM];      // [B,T,C] attention output

// ---------------------------------------------------------------------------
// Kernel 1: QKV projection. C[4096,3072] = x[4096,1024] @ Wqkv[1024,3072] + b
// Classic 128x128x8 SGEMM, 256 threads, 8x8 per-thread tile, scatter epilogue
// into [B,H,T,D] Q/K/V layouts.
// ---------------------------------------------------------------------------
__global__ __launch_bounds__(256) void qkv_gemm(
    const float* __restrict__ A,      // x [4096,1024]
    const float* __restrict__ W,      // Wqkv [1024,3072]
    const float* __restrict__ bias)   // [3072]
{
    const int N = 3 * CDIM;
    const int K = CDIM;
    __shared__ float As[8][128];   // transposed: As[k][m]
    __shared__ float Ws[8][128];   // Ws[k][n]

    const int tid = threadIdx.x;
    const int bm = blockIdx.y * 128;
    const int bn = blockIdx.x * 128;
    const int tx = tid & 15;
    const int ty = tid >> 4;
    const int a_r = tid >> 1, a_c = (tid & 1) * 4;
    const int b_r = tid >> 5, b_c = (tid & 31) * 4;

    const float* Ap = A + (bm + a_r) * K + a_c;
    const float* Wp = W + b_r * N + bn + b_c;

    float acc[8][8];
#pragma unroll
    for (int i = 0; i < 8; i++)
#pragma unroll
        for (int j = 0; j < 8; j++) acc[i][j] = 0.f;

    for (int k0 = 0; k0 < K; k0 += 8) {
        float4 av = *(const float4*)(Ap + k0);
        As[a_c + 0][a_r] = av.x;
        As[a_c + 1][a_r] = av.y;
        As[a_c + 2][a_r] = av.z;
        As[a_c + 3][a_r] = av.w;
        *(float4*)&Ws[b_r][b_c] = *(const float4*)(Wp + k0 * N);
        __syncthreads();
#pragma unroll
        for (int kk = 0; kk < 8; kk++) {
            float4 a0 = *(const float4*)&As[kk][ty * 4];
            float4 a1 = *(const float4*)&As[kk][64 + ty * 4];
            float4 b0 = *(const float4*)&Ws[kk][tx * 4];
            float4 b1 = *(const float4*)&Ws[kk][64 + tx * 4];
            float ar[8] = {a0.x, a0.y, a0.z, a0.w, a1.x, a1.y, a1.z, a1.w};
            float br[8] = {b0.x, b0.y, b0.z, b0.w, b1.x, b1.y, b1.z, b1.w};
#pragma unroll
            for (int i = 0; i < 8; i++)
#pragma unroll
                for (int j = 0; j < 8; j++) acc[i][j] += ar[i] * br[j];
        }
        __syncthreads();
    }

    // Scatter epilogue into Q/K/V [B,H,T,D]
#pragma unroll
    for (int i = 0; i < 8; i++) {
        int m = bm + (i >> 2) * 64 + ty * 4 + (i & 3);
        int bb = m >> 11;        // m / 2048
        int t  = m & 2047;
#pragma unroll
        for (int j = 0; j < 8; j++) {
            int n = bn + (j >> 2) * 64 + tx * 4 + (j & 3);
            float val = acc[i][j] + bias[n];
            int which = n >> 10;     // 0:q 1:k 2:v
            int rem = n & 1023;
            int h = rem >> 6;
            int d = rem & 63;
            int idx = ((bb * NH + h) * TLEN + t) * HD + d;
            float* dst = (which == 0) ? g_q : (which == 1) ? g_k : g_v;
            dst[idx] = val;
        }
    }
}

// ---------------------------------------------------------------------------
// Kernel 2: attention with inverted-causal mask (keep k >= q).
// One block per (b*h, 64-query tile). K/V 64x64 tiles staged in smem,
// online softmax, fp32 accumulators. Tiles with k0 < q0 are fully masked
// and skipped entirely (loop starts at k0 = q0).
// Thread layout: 128 threads; thread owns (row = tid>>1) and half of D
// (half = tid&1 -> D[half*32 .. half*32+31]). Score dot combined via shfl.
// ---------------------------------------------------------------------------
__global__ __launch_bounds__(128) void attn_kernel()
{
    __shared__ float ks[64][64];
    __shared__ float vs[64][64];

    const int tid = threadIdx.x;
    const int bh = blockIdx.y;            // b*16 + h
    const int q0 = blockIdx.x * 64;

    const float* Qb = g_q + bh * TLEN * HD;
    const float* Kb = g_k + bh * TLEN * HD;
    const float* Vb = g_v + bh * TLEN * HD;

    const int row = tid >> 1;
    const int half = tid & 1;

    float qf[32];
    {
        const float4* qp = (const float4*)(Qb + (q0 + row) * HD + half * 32);
#pragma unroll
        for (int i = 0; i < 8; i++) {
            float4 v = qp[i];
            qf[4 * i + 0] = v.x * SCALE;
            qf[4 * i + 1] = v.y * SCALE;
            qf[4 * i + 2] = v.z * SCALE;
            qf[4 * i + 3] = v.w * SCALE;
        }
    }

    float m = -1e30f, l = 0.f;
    float acc[32];
#pragma unroll
    for (int d = 0; d < 32; d++) acc[d] = 0.f;

    for (int k0 = q0; k0 < TLEN; k0 += 64) {
        __syncthreads();   // previous-iteration smem reads done
#pragma unroll
        for (int i = 0; i < 8; i++) {
            int idx = tid + i * 128;         // float4 index 0..1023
            int r = idx >> 4;
            int c = (idx & 15) * 4;
            *(float4*)&ks[r][c] = *(const float4*)(Kb + (k0 + r) * HD + c);
            *(float4*)&vs[r][c] = *(const float4*)(Vb + (k0 + r) * HD + c);
        }
        __syncthreads();

        float s[64];
#pragma unroll
        for (int j = 0; j < 64; j++) {
            float p = 0.f;
            const float4* kp = (const float4*)&ks[j][half * 32];
#pragma unroll
            for (int i = 0; i < 8; i++) {
                float4 kv = kp[i];
                p += qf[4 * i + 0] * kv.x + qf[4 * i + 1] * kv.y
                   + qf[4 * i + 2] * kv.z + qf[4 * i + 3] * kv.w;
            }
            p += __shfl_xor_sync(0xffffffffu, p, 1);   // combine halves
            s[j] = p;
        }

        if (k0 == q0) {   // only the diagonal tile is partially masked
#pragma unroll
            for (int j = 0; j < 64; j++)
                if (j < row) s[j] = -1e30f;   // mask keys with k < q
        }

        float tmax = m;
#pragma unroll
        for (int j = 0; j < 64; j++) tmax = fmaxf(tmax, s[j]);
        float corr = __expf(m - tmax);
        m = tmax;
        l *= corr;
#pragma unroll
        for (int d = 0; d < 32; d++) acc[d] *= corr;

#pragma unroll
        for (int j = 0; j < 64; j++) {
            float p = __expf(s[j] - m);
            l += p;
            const float4* vp = (const float4*)&vs[j][half * 32];
#pragma unroll
            for (int i = 0; i < 8; i++) {
                float4 vv = vp[i];
                acc[4 * i + 0] += p * vv.x;
                acc[4 * i + 1] += p * vv.y;
                acc[4 * i + 2] += p * vv.z;
                acc[4 * i + 3] += p * vv.w;
            }
        }
    }

    const int b = bh >> 4;
    const int h = bh & 15;
    const float inv = 1.f / l;
    float* yp = g_y + (b * TLEN + q0 + row) * CDIM + h * HD + half * 32;
#pragma unroll
    for (int i = 0; i < 8; i++) {
        float4 o;
        o.x = acc[4 * i + 0] * inv;
        o.y = acc[4 * i + 1] * inv;
        o.z = acc[4 * i + 2] * inv;
        o.w = acc[4 * i + 3] * inv;
        *(float4*)(yp + 4 * i) = o;
    }
}

// ---------------------------------------------------------------------------
// Kernel 3: output projection. out[4096,1024] = y[4096,1024] @ Wo[1024,1024] + bo
// ---------------------------------------------------------------------------
__global__ __launch_bounds__(256) void out_gemm(
    const float* __restrict__ W,      // Wo [1024,1024]
    const float* __restrict__ bias,   // [1024]
    float* __restrict__ C)            // out [4096,1024]
{
    const int N = CDIM;
    const int K = CDIM;
    __shared__ float As[8][128];
    __shared__ float Ws[8][128];

    const int tid = threadIdx.x;
    const int bm = blockIdx.y * 128;
    const int bn = blockIdx.x * 128;
    const int tx = tid & 15;
    const int ty = tid >> 4;
    const int a_r = tid >> 1, a_c = (tid & 1) * 4;
    const int b_r = tid >> 5, b_c = (tid & 31) * 4;

    const float* Ap = g_y + (bm + a_r) * K + a_c;
    const float* Wp = W + b_r * N + bn + b_c;

    float acc[8][8];
#pragma unroll
    for (int i = 0; i < 8; i++)
#pragma unroll
        for (int j = 0; j < 8; j++) acc[i][j] = 0.f;

    for (int k0 = 0; k0 < K; k0 += 8) {
        float4 av = *(const float4*)(Ap + k0);
        As[a_c + 0][a_r] = av.x;
        As[a_c + 1][a_r] = av.y;
        As[a_c + 2][a_r] = av.z;
        As[a_c + 3][a_r] = av.w;
        *(float4*)&Ws[b_r][b_c] = *(const float4*)(Wp + k0 * N);
        __syncthreads();
#pragma unroll
        for (int kk = 0; kk < 8; kk++) {
            float4 a0 = *(const float4*)&As[kk][ty * 4];
            float4 a1 = *(const float4*)&As[kk][64 + ty * 4];
            float4 b0 = *(const float4*)&Ws[kk][tx * 4];
            float4 b1 = *(const float4*)&Ws[kk][64 + tx * 4];
            float ar[8] = {a0.x, a0.y, a0.z, a0.w, a1.x, a1.y, a1.z, a1.w};
            float br[8] = {b0.x, b0.y, b0.z, b0.w, b1.x, b1.y, b1.z, b1.w};
#pragma unroll
            for (int i = 0; i < 8; i++)
#pragma unroll
                for (int j = 0; j < 8; j++) acc[i][j] += ar[i] * br[j];
        }
        __syncthreads();
    }

#pragma unroll
    for (int i = 0; i < 8; i++) {
        int mrow = bm + (i >> 2) * 64 + ty * 4 + (i & 3);
#pragma unroll
        for (int j = 0; j < 8; j++) {
            int n = bn + (j >> 2) * 64 + tx * 4 + (j & 3);
            C[mrow * N + n] = acc[i][j] + bias[n];
        }
    }
}

// ---------------------------------------------------------------------------
extern "C" void kernel_launch(void* const* d_in, const int* in_sizes, int n_in,
                              void* d_out, int out_size)
{
    const float* x    = (const float*)d_in[0];
    const float* Wqkv = (const float*)d_in[1];
    const float* bqkv = (const float*)d_in[2];
    const float* Wo   = (const float*)d_in[3];
    const float* bo   = (const float*)d_in[4];
    float* out = (float*)d_out;

    qkv_gemm<<<dim3(24, 32), 256>>>(x, Wqkv, bqkv);   // N=3072/128, M=4096/128
    attn_kernel<<<dim3(32, 32), 128>>>();             // T/64 q-tiles, B*H
    out_gemm<<<dim3(8, 32), 256>>>(Wo, bo, out);      // N=1024/128, M=4096/128
}

// round 5
// speedup vs baseline: 1.4885x; 1.4885x over previous
#include <cuda_runtime.h>
#include <cstdint>

// Problem constants
#define BSZ   2
#define TLEN  2048
#define CDIM  1024
#define NH    16
#define HD    64
#define SCALE 0.125f   // 1/sqrt(64)

// Scratch (allocation-free rule: __device__ globals)
static __device__ float g_q[BSZ * NH * TLEN * HD];   // [B,H,T,D]
static __device__ float g_k[BSZ * NH * TLEN * HD];
static __device__ float g_v[BSZ * NH * TLEN * HD];
static __device__ float g_y[BSZ * TLEN * CDIM];      // [B,T,C] attention output

// ---------------------------------------------------------------------------
// tf32 helpers
// ---------------------------------------------------------------------------
__device__ __forceinline__ uint32_t f2tf(float x) {
    uint32_t t;
    asm("cvt.rna.tf32.f32 %0, %1;" : "=r"(t) : "f"(x));
    return t;
}

__device__ __forceinline__ void mma_tf32(float c[4],
                                         const uint32_t a[4],
                                         uint32_t b0, uint32_t b1) {
    asm volatile(
        "mma.sync.aligned.m16n8k8.row.col.f32.tf32.tf32.f32 "
        "{%0,%1,%2,%3},{%4,%5,%6,%7},{%8,%9},{%0,%1,%2,%3};"
        : "+f"(c[0]), "+f"(c[1]), "+f"(c[2]), "+f"(c[3])
        : "r"(a[0]), "r"(a[1]), "r"(a[2]), "r"(a[3]), "r"(b0), "r"(b1));
}

// ---------------------------------------------------------------------------
// Shared tf32 GEMM core: 128x128 block tile, 8 warps (warp tile 64x32),
// K-chunk 16, double-buffered smem, conflict-free fragment LDS.
//   A: row-major [M,K] (M = 4096)
//   W: row-major [K,N]
// Fragment layouts (m16n8k8): g = lane>>2, tig = lane&3
//   a0=A[g][tig] a1=A[g+8][tig] a2=A[g][tig+4] a3=A[g+8][tig+4]
//   b0=B[tig][g] b1=B[tig+4][g]
//   c0=C[g][2t]  c1=C[g][2t+1]  c2=C[g+8][2t]  c3=C[g+8][2t+1]
// smem strides: As stride 20 (bank = 4g+tig, injective over 8x4),
//               Ws stride 136 (bank = 8tig+g, injective over 4x8).
// ---------------------------------------------------------------------------
#define AS_STRIDE 20
#define WS_STRIDE 136

template<int N, int K>
__device__ __forceinline__ void gemm128_tf32(const float* __restrict__ A,
                                             const float* __restrict__ W,
                                             float acc[4][4][4])
{
    __shared__ uint32_t As[2][128 * AS_STRIDE];   // 2 x 10240 B
    __shared__ uint32_t Ws[2][16 * WS_STRIDE];    // 2 x  8704 B

    const int tid  = threadIdx.x;
    const int warp = tid >> 5;
    const int lane = tid & 31;
    const int g    = lane >> 2;
    const int tig  = lane & 3;
    const int bm   = blockIdx.y * 128;
    const int bn   = blockIdx.x * 128;
    const int wm   = (warp & 1) * 64;
    const int wn   = (warp >> 1) * 32;

    // A tile load map: 512 float4 per chunk, 2 per thread
    const int am0 = tid >> 2;           // 0..63  (second: +64)
    const int akq = (tid & 3) * 4;      // k offset within chunk
    // W tile load map: 512 float4 per chunk, 2 per thread
    const int wk0 = tid >> 5;           // 0..7   (second: +8)
    const int wn4 = (tid & 31) * 4;

    const float* Ap0 = A + (size_t)(bm + am0) * K + akq;
    const float* Ap1 = Ap0 + (size_t)64 * K;
    const float* Wp0 = W + (size_t)wk0 * N + bn + wn4;
    const float* Wp1 = Wp0 + (size_t)8 * N;

#pragma unroll
    for (int i = 0; i < 4; i++)
#pragma unroll
        for (int j = 0; j < 4; j++)
#pragma unroll
            for (int e = 0; e < 4; e++) acc[i][j][e] = 0.f;

    float4 a0v, a1v, w0v, w1v;

    auto sts = [&](int p) {
        uint4 t;
        t.x = f2tf(a0v.x); t.y = f2tf(a0v.y); t.z = f2tf(a0v.z); t.w = f2tf(a0v.w);
        *(uint4*)&As[p][am0 * AS_STRIDE + akq] = t;
        t.x = f2tf(a1v.x); t.y = f2tf(a1v.y); t.z = f2tf(a1v.z); t.w = f2tf(a1v.w);
        *(uint4*)&As[p][(am0 + 64) * AS_STRIDE + akq] = t;
        t.x = f2tf(w0v.x); t.y = f2tf(w0v.y); t.z = f2tf(w0v.z); t.w = f2tf(w0v.w);
        *(uint4*)&Ws[p][wk0 * WS_STRIDE + wn4] = t;
        t.x = f2tf(w1v.x); t.y = f2tf(w1v.y); t.z = f2tf(w1v.z); t.w = f2tf(w1v.w);
        *(uint4*)&Ws[p][(wk0 + 8) * WS_STRIDE + wn4] = t;
    };

    // prologue: chunk 0
    a0v = *(const float4*)(Ap0);
    a1v = *(const float4*)(Ap1);
    w0v = *(const float4*)(Wp0);
    w1v = *(const float4*)(Wp1);
    sts(0);
    __syncthreads();

    const int NC = K / 16;
    int p = 0;
    for (int c = 0; c < NC; c++) {
        if (c + 1 < NC) {   // prefetch next chunk to registers
            const int off = (c + 1) * 16;
            a0v = *(const float4*)(Ap0 + off);
            a1v = *(const float4*)(Ap1 + off);
            w0v = *(const float4*)(Wp0 + (size_t)off * N);
            w1v = *(const float4*)(Wp1 + (size_t)off * N);
        }
#pragma unroll
        for (int ks = 0; ks < 2; ks++) {
            const int kb = ks * 8;
            uint32_t af[4][4];
#pragma unroll
            for (int fm = 0; fm < 4; fm++) {
                const int r = wm + fm * 16 + g;
                af[fm][0] = As[p][r * AS_STRIDE + kb + tig];
                af[fm][1] = As[p][(r + 8) * AS_STRIDE + kb + tig];
                af[fm][2] = As[p][r * AS_STRIDE + kb + tig + 4];
                af[fm][3] = As[p][(r + 8) * AS_STRIDE + kb + tig + 4];
            }
            uint32_t bf[4][2];
#pragma unroll
            for (int fn = 0; fn < 4; fn++) {
                const int nn = wn + fn * 8 + g;
                bf[fn][0] = Ws[p][(kb + tig) * WS_STRIDE + nn];
                bf[fn][1] = Ws[p][(kb + tig + 4) * WS_STRIDE + nn];
            }
#pragma unroll
            for (int fm = 0; fm < 4; fm++)
#pragma unroll
                for (int fn = 0; fn < 4; fn++)
                    mma_tf32(acc[fm][fn], af[fm], bf[fn][0], bf[fn][1]);
        }
        if (c + 1 < NC) {
            // buf 1-p: all reads finished before the last __syncthreads()
            sts(1 - p);
            __syncthreads();
            p ^= 1;
        }
    }
}

// ---------------------------------------------------------------------------
// Kernel 1: QKV projection (tensor core) with scatter epilogue into [B,H,T,D]
// ---------------------------------------------------------------------------
__global__ __launch_bounds__(256, 2) void qkv_gemm(
    const float* __restrict__ A,      // x [4096,1024]
    const float* __restrict__ W,      // Wqkv [1024,3072]
    const float* __restrict__ bias)   // [3072]
{
    float acc[4][4][4];
    gemm128_tf32<3 * CDIM, CDIM>(A, W, acc);

    const int tid  = threadIdx.x;
    const int warp = tid >> 5;
    const int lane = tid & 31;
    const int g    = lane >> 2;
    const int tig  = lane & 3;
    const int bm   = blockIdx.y * 128;
    const int bn   = blockIdx.x * 128;
    const int wm   = (warp & 1) * 64;
    const int wn   = (warp >> 1) * 32;

#pragma unroll
    for (int fm = 0; fm < 4; fm++) {
#pragma unroll
        for (int fn = 0; fn < 4; fn++) {
            const int row0 = bm + wm + fm * 16 + g;
            const int col0 = bn + wn + fn * 8 + tig * 2;
#pragma unroll
            for (int e = 0; e < 4; e++) {
                const int m = row0 + (e >> 1) * 8;
                const int n = col0 + (e & 1);
                const float v = acc[fm][fn][e] + bias[n];
                const int bb    = m >> 11;
                const int t     = m & 2047;
                const int which = n >> 10;
                const int rem   = n & 1023;
                const int h     = rem >> 6;
                const int d     = rem & 63;
                float* dst = (which == 0) ? g_q : (which == 1) ? g_k : g_v;
                dst[((bb * NH + h) * TLEN + t) * HD + d] = v;
            }
        }
    }
}

// ---------------------------------------------------------------------------
// Kernel 2: attention (unchanged SIMT flash, inverted-causal mask k >= q)
// ---------------------------------------------------------------------------
__global__ __launch_bounds__(128) void attn_kernel()
{
    __shared__ float ks[64][64];
    __shared__ float vs[64][64];

    const int tid = threadIdx.x;
    const int bh = blockIdx.y;            // b*16 + h
    const int q0 = blockIdx.x * 64;

    const float* Qb = g_q + bh * TLEN * HD;
    const float* Kb = g_k + bh * TLEN * HD;
    const float* Vb = g_v + bh * TLEN * HD;

    const int row = tid >> 1;
    const int half = tid & 1;

    float qf[32];
    {
        const float4* qp = (const float4*)(Qb + (q0 + row) * HD + half * 32);
#pragma unroll
        for (int i = 0; i < 8; i++) {
            float4 v = qp[i];
            qf[4 * i + 0] = v.x * SCALE;
            qf[4 * i + 1] = v.y * SCALE;
            qf[4 * i + 2] = v.z * SCALE;
            qf[4 * i + 3] = v.w * SCALE;
        }
    }

    float m = -1e30f, l = 0.f;
    float acc[32];
#pragma unroll
    for (int d = 0; d < 32; d++) acc[d] = 0.f;

    for (int k0 = q0; k0 < TLEN; k0 += 64) {
        __syncthreads();
#pragma unroll
        for (int i = 0; i < 8; i++) {
            int idx = tid + i * 128;
            int r = idx >> 4;
            int c = (idx & 15) * 4;
            *(float4*)&ks[r][c] = *(const float4*)(Kb + (k0 + r) * HD + c);
            *(float4*)&vs[r][c] = *(const float4*)(Vb + (k0 + r) * HD + c);
        }
        __syncthreads();

        float s[64];
#pragma unroll
        for (int j = 0; j < 64; j++) {
            float p = 0.f;
            const float4* kp = (const float4*)&ks[j][half * 32];
#pragma unroll
            for (int i = 0; i < 8; i++) {
                float4 kv = kp[i];
                p += qf[4 * i + 0] * kv.x + qf[4 * i + 1] * kv.y
                   + qf[4 * i + 2] * kv.z + qf[4 * i + 3] * kv.w;
            }
            p += __shfl_xor_sync(0xffffffffu, p, 1);
            s[j] = p;
        }

        if (k0 == q0) {
#pragma unroll
            for (int j = 0; j < 64; j++)
                if (j < row) s[j] = -1e30f;   // mask keys with k < q
        }

        float tmax = m;
#pragma unroll
        for (int j = 0; j < 64; j++) tmax = fmaxf(tmax, s[j]);
        float corr = __expf(m - tmax);
        m = tmax;
        l *= corr;
#pragma unroll
        for (int d = 0; d < 32; d++) acc[d] *= corr;

#pragma unroll
        for (int j = 0; j < 64; j++) {
            float p = __expf(s[j] - m);
            l += p;
            const float4* vp = (const float4*)&vs[j][half * 32];
#pragma unroll
            for (int i = 0; i < 8; i++) {
                float4 vv = vp[i];
                acc[4 * i + 0] += p * vv.x;
                acc[4 * i + 1] += p * vv.y;
                acc[4 * i + 2] += p * vv.z;
                acc[4 * i + 3] += p * vv.w;
            }
        }
    }

    const int b = bh >> 4;
    const int h = bh & 15;
    const float inv = 1.f / l;
    float* yp = g_y + (b * TLEN + q0 + row) * CDIM + h * HD + half * 32;
#pragma unroll
    for (int i = 0; i < 8; i++) {
        float4 o;
        o.x = acc[4 * i + 0] * inv;
        o.y = acc[4 * i + 1] * inv;
        o.z = acc[4 * i + 2] * inv;
        o.w = acc[4 * i + 3] * inv;
        *(float4*)(yp + 4 * i) = o;
    }
}

// ---------------------------------------------------------------------------
// Kernel 3: output projection (tensor core) + bias
// ---------------------------------------------------------------------------
__global__ __launch_bounds__(256, 2) void out_gemm(
    const float* __restrict__ W,      // Wo [1024,1024]
    const float* __restrict__ bias,   // [1024]
    float* __restrict__ C)            // out [4096,1024]
{
    float acc[4][4][4];
    gemm128_tf32<CDIM, CDIM>(g_y, W, acc);

    const int tid  = threadIdx.x;
    const int warp = tid >> 5;
    const int lane = tid & 31;
    const int g    = lane >> 2;
    const int tig  = lane & 3;
    const int bm   = blockIdx.y * 128;
    const int bn   = blockIdx.x * 128;
    const int wm   = (warp & 1) * 64;
    const int wn   = (warp >> 1) * 32;

#pragma unroll
    for (int fm = 0; fm < 4; fm++) {
#pragma unroll
        for (int fn = 0; fn < 4; fn++) {
            const int row0 = bm + wm + fm * 16 + g;
            const int col0 = bn + wn + fn * 8 + tig * 2;
            C[(size_t)row0 * CDIM + col0]           = acc[fm][fn][0] + bias[col0];
            C[(size_t)row0 * CDIM + col0 + 1]       = acc[fm][fn][1] + bias[col0 + 1];
            C[(size_t)(row0 + 8) * CDIM + col0]     = acc[fm][fn][2] + bias[col0];
            C[(size_t)(row0 + 8) * CDIM + col0 + 1] = acc[fm][fn][3] + bias[col0 + 1];
        }
    }
}

// ---------------------------------------------------------------------------
extern "C" void kernel_launch(void* const* d_in, const int* in_sizes, int n_in,
                              void* d_out, int out_size)
{
    const float* x    = (const float*)d_in[0];
    const float* Wqkv = (const float*)d_in[1];
    const float* bqkv = (const float*)d_in[2];
    const float* Wo   = (const float*)d_in[3];
    const float* bo   = (const float*)d_in[4];
    float* out = (float*)d_out;

    qkv_gemm<<<dim3(24, 32), 256>>>(x, Wqkv, bqkv);   // N=3072/128, M=4096/128
    attn_kernel<<<dim3(32, 32), 128>>>();             // T/64 q-tiles, B*H
    out_gemm<<<dim3(8, 32), 256>>>(Wo, bo, out);      // N=1024/128, M=4096/128
}

// round 6
// speedup vs baseline: 5.0933x; 3.4217x over previous
#include <cuda_runtime.h>
#include <cstdint>

// Problem constants
#define BSZ   2
#define TLEN  2048
#define CDIM  1024
#define NH    16
#define HD    64
#define SCALE 0.125f   // 1/sqrt(64)

// Scratch (allocation-free rule: __device__ globals)
// Q/K/V stored as tf32 bit patterns (Q pre-scaled by SCALE).
static __device__ uint32_t g_q[BSZ * NH * TLEN * HD];   // [B,H,T,D]
static __device__ uint32_t g_k[BSZ * NH * TLEN * HD];
static __device__ uint32_t g_v[BSZ * NH * TLEN * HD];
static __device__ float    g_y[BSZ * TLEN * CDIM];      // [B,T,C] attn output (fp32)

// ---------------------------------------------------------------------------
// tf32 helpers
// ---------------------------------------------------------------------------
__device__ __forceinline__ uint32_t f2tf(float x) {
    uint32_t t;
    asm("cvt.rna.tf32.f32 %0, %1;" : "=r"(t) : "f"(x));
    return t;
}

__device__ __forceinline__ void mma_tf32(float c[4],
                                         const uint32_t a[4],
                                         uint32_t b0, uint32_t b1) {
    asm volatile(
        "mma.sync.aligned.m16n8k8.row.col.f32.tf32.tf32.f32 "
        "{%0,%1,%2,%3},{%4,%5,%6,%7},{%8,%9},{%0,%1,%2,%3};"
        : "+f"(c[0]), "+f"(c[1]), "+f"(c[2]), "+f"(c[3])
        : "r"(a[0]), "r"(a[1]), "r"(a[2]), "r"(a[3]), "r"(b0), "r"(b1));
}

// ---------------------------------------------------------------------------
// Shared tf32 GEMM core (unchanged from round 4): 128x128 block tile, 8 warps
// (warp tile 64x32), K-chunk 16, double-buffered smem, conflict-free LDS.
// ---------------------------------------------------------------------------
#define AS_STRIDE 20
#define WS_STRIDE 136

template<int N, int K>
__device__ __forceinline__ void gemm128_tf32(const float* __restrict__ A,
                                             const float* __restrict__ W,
                                             float acc[4][4][4])
{
    __shared__ uint32_t As[2][128 * AS_STRIDE];
    __shared__ uint32_t Ws[2][16 * WS_STRIDE];

    const int tid  = threadIdx.x;
    const int warp = tid >> 5;
    const int lane = tid & 31;
    const int g    = lane >> 2;
    const int tig  = lane & 3;
    const int bm   = blockIdx.y * 128;
    const int bn   = blockIdx.x * 128;
    const int wm   = (warp & 1) * 64;
    const int wn   = (warp >> 1) * 32;

    const int am0 = tid >> 2;
    const int akq = (tid & 3) * 4;
    const int wk0 = tid >> 5;
    const int wn4 = (tid & 31) * 4;

    const float* Ap0 = A + (size_t)(bm + am0) * K + akq;
    const float* Ap1 = Ap0 + (size_t)64 * K;
    const float* Wp0 = W + (size_t)wk0 * N + bn + wn4;
    const float* Wp1 = Wp0 + (size_t)8 * N;

#pragma unroll
    for (int i = 0; i < 4; i++)
#pragma unroll
        for (int j = 0; j < 4; j++)
#pragma unroll
            for (int e = 0; e < 4; e++) acc[i][j][e] = 0.f;

    float4 a0v, a1v, w0v, w1v;

    auto sts = [&](int p) {
        uint4 t;
        t.x = f2tf(a0v.x); t.y = f2tf(a0v.y); t.z = f2tf(a0v.z); t.w = f2tf(a0v.w);
        *(uint4*)&As[p][am0 * AS_STRIDE + akq] = t;
        t.x = f2tf(a1v.x); t.y = f2tf(a1v.y); t.z = f2tf(a1v.z); t.w = f2tf(a1v.w);
        *(uint4*)&As[p][(am0 + 64) * AS_STRIDE + akq] = t;
        t.x = f2tf(w0v.x); t.y = f2tf(w0v.y); t.z = f2tf(w0v.z); t.w = f2tf(w0v.w);
        *(uint4*)&Ws[p][wk0 * WS_STRIDE + wn4] = t;
        t.x = f2tf(w1v.x); t.y = f2tf(w1v.y); t.z = f2tf(w1v.z); t.w = f2tf(w1v.w);
        *(uint4*)&Ws[p][(wk0 + 8) * WS_STRIDE + wn4] = t;
    };

    a0v = *(const float4*)(Ap0);
    a1v = *(const float4*)(Ap1);
    w0v = *(const float4*)(Wp0);
    w1v = *(const float4*)(Wp1);
    sts(0);
    __syncthreads();

    const int NC = K / 16;
    int p = 0;
    for (int c = 0; c < NC; c++) {
        if (c + 1 < NC) {
            const int off = (c + 1) * 16;
            a0v = *(const float4*)(Ap0 + off);
            a1v = *(const float4*)(Ap1 + off);
            w0v = *(const float4*)(Wp0 + (size_t)off * N);
            w1v = *(const float4*)(Wp1 + (size_t)off * N);
        }
#pragma unroll
        for (int ks = 0; ks < 2; ks++) {
            const int kb = ks * 8;
            uint32_t af[4][4];
#pragma unroll
            for (int fm = 0; fm < 4; fm++) {
                const int r = wm + fm * 16 + g;
                af[fm][0] = As[p][r * AS_STRIDE + kb + tig];
                af[fm][1] = As[p][(r + 8) * AS_STRIDE + kb + tig];
                af[fm][2] = As[p][r * AS_STRIDE + kb + tig + 4];
                af[fm][3] = As[p][(r + 8) * AS_STRIDE + kb + tig + 4];
            }
            uint32_t bf[4][2];
#pragma unroll
            for (int fn = 0; fn < 4; fn++) {
                const int nn = wn + fn * 8 + g;
                bf[fn][0] = Ws[p][(kb + tig) * WS_STRIDE + nn];
                bf[fn][1] = Ws[p][(kb + tig + 4) * WS_STRIDE + nn];
            }
#pragma unroll
            for (int fm = 0; fm < 4; fm++)
#pragma unroll
                for (int fn = 0; fn < 4; fn++)
                    mma_tf32(acc[fm][fn], af[fm], bf[fn][0], bf[fn][1]);
        }
        if (c + 1 < NC) {
            sts(1 - p);
            __syncthreads();
            p ^= 1;
        }
    }
}

// ---------------------------------------------------------------------------
// Kernel 1: QKV projection; epilogue scatters tf32 bits into [B,H,T,D]
// (Q pre-scaled by SCALE — exact power of two, no extra rounding error).
// ---------------------------------------------------------------------------
__global__ __launch_bounds__(256, 2) void qkv_gemm(
    const float* __restrict__ A,      // x [4096,1024]
    const float* __restrict__ W,      // Wqkv [1024,3072]
    const float* __restrict__ bias)   // [3072]
{
    float acc[4][4][4];
    gemm128_tf32<3 * CDIM, CDIM>(A, W, acc);

    const int tid  = threadIdx.x;
    const int warp = tid >> 5;
    const int lane = tid & 31;
    const int g    = lane >> 2;
    const int tig  = lane & 3;
    const int bm   = blockIdx.y * 128;
    const int bn   = blockIdx.x * 128;
    const int wm   = (warp & 1) * 64;
    const int wn   = (warp >> 1) * 32;

#pragma unroll
    for (int fm = 0; fm < 4; fm++) {
#pragma unroll
        for (int fn = 0; fn < 4; fn++) {
            const int row0 = bm + wm + fm * 16 + g;
            const int col0 = bn + wn + fn * 8 + tig * 2;
#pragma unroll
            for (int e = 0; e < 4; e++) {
                const int m = row0 + (e >> 1) * 8;
                const int n = col0 + (e & 1);
                float v = acc[fm][fn][e] + bias[n];
                const int bb    = m >> 11;
                const int t     = m & 2047;
                const int which = n >> 10;
                const int rem   = n & 1023;
                const int h     = rem >> 6;
                const int d     = rem & 63;
                if (which == 0) v *= SCALE;
                uint32_t* dst = (which == 0) ? g_q : (which == 1) ? g_k : g_v;
                dst[((bb * NH + h) * TLEN + t) * HD + d] = f2tf(v);
            }
        }
    }
}

// ---------------------------------------------------------------------------
// Kernel 2: tensor-core flash attention, inverted-causal mask (keep k >= q).
// Block = 4 warps = 64 q-rows; warp owns 16 rows (m16). K/V 64-tiles in smem
// (tf32, conflict-free strides). QK^T and PV via m16n8k8 tf32 mma; online
// softmax on C-fragments; P C-frag -> A-frag via shfl transpose.
// Fragment maps (lane = 4g+tig):
//   A: a0=A[g][tig] a1=A[g+8][tig] a2=A[g][tig+4] a3=A[g+8][tig+4]
//   B: b0=B[k=tig][n=g] b1=B[k=tig+4][n=g]
//   C: c0=C[g][2tig] c1=C[g][2tig+1] c2=C[g+8][2tig] c3=C[g+8][2tig+1]
// ---------------------------------------------------------------------------
#define KS_STRIDE 68   // bank = 4g+tig  (injective)
#define VS_STRIDE 72   // bank = 8tig+g  (injective)

__global__ __launch_bounds__(128) void attn_kernel()
{
    __shared__ uint32_t Ks[64 * KS_STRIDE];
    __shared__ uint32_t Vs[64 * VS_STRIDE];

    const int tid  = threadIdx.x;
    const int warp = tid >> 5;
    const int lane = tid & 31;
    const int g    = lane >> 2;
    const int tig  = lane & 3;
    const int bh   = blockIdx.y;          // b*16 + h
    const int q0   = blockIdx.x * 64;

    const uint32_t* Qb = g_q + (size_t)bh * TLEN * HD;
    const uint32_t* Kb = g_k + (size_t)bh * TLEN * HD;
    const uint32_t* Vb = g_v + (size_t)bh * TLEN * HD;

    const int row_lo = q0 + warp * 16 + g;   // this thread's low q-row

    // Q fragments: register-resident for the whole KV loop
    uint32_t aQ[8][4];
#pragma unroll
    for (int kk = 0; kk < 8; kk++) {
        aQ[kk][0] = Qb[(size_t)row_lo * HD + kk * 8 + tig];
        aQ[kk][1] = Qb[(size_t)(row_lo + 8) * HD + kk * 8 + tig];
        aQ[kk][2] = Qb[(size_t)row_lo * HD + kk * 8 + tig + 4];
        aQ[kk][3] = Qb[(size_t)(row_lo + 8) * HD + kk * 8 + tig + 4];
    }

    float o[8][4];
#pragma unroll
    for (int dn = 0; dn < 8; dn++)
#pragma unroll
        for (int e = 0; e < 4; e++) o[dn][e] = 0.f;
    float mrow[2] = {-1e30f, -1e30f};
    float lrow[2] = {0.f, 0.f};

    for (int k0 = q0; k0 < TLEN; k0 += 64) {
        __syncthreads();   // previous-iteration smem reads done
#pragma unroll
        for (int i = 0; i < 8; i++) {
            const int idx = tid + i * 128;     // 0..1023 uint4 slots
            const int r = idx >> 4;
            const int c = (idx & 15) << 2;
            *(uint4*)&Ks[r * KS_STRIDE + c] = *(const uint4*)(Kb + (size_t)(k0 + r) * HD + c);
            *(uint4*)&Vs[r * VS_STRIDE + c] = *(const uint4*)(Vb + (size_t)(k0 + r) * HD + c);
        }
        __syncthreads();

        // S = Q K^T  (scale pre-folded into Q)
        float s[8][4];
#pragma unroll
        for (int fn = 0; fn < 8; fn++) {
#pragma unroll
            for (int e = 0; e < 4; e++) s[fn][e] = 0.f;
#pragma unroll
            for (int kk = 0; kk < 8; kk++) {
                const uint32_t b0 = Ks[(fn * 8 + g) * KS_STRIDE + kk * 8 + tig];
                const uint32_t b1 = Ks[(fn * 8 + g) * KS_STRIDE + kk * 8 + tig + 4];
                mma_tf32(s[fn], aQ[kk], b0, b1);
            }
        }

        // diagonal tile: mask keys with (global key) < (global q row)
        if (k0 == q0) {
#pragma unroll
            for (int fn = 0; fn < 8; fn++)
#pragma unroll
                for (int e = 0; e < 4; e++) {
                    const int key = fn * 8 + tig * 2 + (e & 1);
                    const int qr  = warp * 16 + g + ((e >> 1) << 3);
                    if (key < qr) s[fn][e] = -1e30f;
                }
        }

        // online softmax: row max (reduce over own 16 cols, then tig group)
        float rm0 = -1e30f, rm1 = -1e30f;
#pragma unroll
        for (int fn = 0; fn < 8; fn++) {
            rm0 = fmaxf(rm0, fmaxf(s[fn][0], s[fn][1]));
            rm1 = fmaxf(rm1, fmaxf(s[fn][2], s[fn][3]));
        }
        rm0 = fmaxf(rm0, __shfl_xor_sync(0xffffffffu, rm0, 1));
        rm0 = fmaxf(rm0, __shfl_xor_sync(0xffffffffu, rm0, 2));
        rm1 = fmaxf(rm1, __shfl_xor_sync(0xffffffffu, rm1, 1));
        rm1 = fmaxf(rm1, __shfl_xor_sync(0xffffffffu, rm1, 2));

        const float mn0 = fmaxf(mrow[0], rm0);
        const float mn1 = fmaxf(mrow[1], rm1);
        const float c0 = __expf(mrow[0] - mn0);
        const float c1 = __expf(mrow[1] - mn1);
        mrow[0] = mn0; mrow[1] = mn1;
        lrow[0] *= c0; lrow[1] *= c1;
#pragma unroll
        for (int dn = 0; dn < 8; dn++) {
            o[dn][0] *= c0; o[dn][1] *= c0;
            o[dn][2] *= c1; o[dn][3] *= c1;
        }

        // P = exp(S - m), row sums
        float ps0 = 0.f, ps1 = 0.f;
#pragma unroll
        for (int fn = 0; fn < 8; fn++) {
            s[fn][0] = __expf(s[fn][0] - mn0);
            s[fn][1] = __expf(s[fn][1] - mn0);
            s[fn][2] = __expf(s[fn][2] - mn1);
            s[fn][3] = __expf(s[fn][3] - mn1);
            ps0 += s[fn][0] + s[fn][1];
            ps1 += s[fn][2] + s[fn][3];
        }
        ps0 += __shfl_xor_sync(0xffffffffu, ps0, 1);
        ps0 += __shfl_xor_sync(0xffffffffu, ps0, 2);
        ps1 += __shfl_xor_sync(0xffffffffu, ps1, 1);
        ps1 += __shfl_xor_sync(0xffffffffu, ps1, 2);
        lrow[0] += ps0; lrow[1] += ps1;

        // O += P V : shfl-transpose P C-frags into A-frags, then mma
        const int src1 = (g << 2) + (tig >> 1);
        const int src2 = src1 + 2;
        const bool odd = (tig & 1) != 0;
#pragma unroll
        for (int fn = 0; fn < 8; fn++) {
            const float x0 = __shfl_sync(0xffffffffu, s[fn][0], src1);
            const float x1 = __shfl_sync(0xffffffffu, s[fn][1], src1);
            const float x2 = __shfl_sync(0xffffffffu, s[fn][2], src1);
            const float x3 = __shfl_sync(0xffffffffu, s[fn][3], src1);
            const float y0 = __shfl_sync(0xffffffffu, s[fn][0], src2);
            const float y1 = __shfl_sync(0xffffffffu, s[fn][1], src2);
            const float y2 = __shfl_sync(0xffffffffu, s[fn][2], src2);
            const float y3 = __shfl_sync(0xffffffffu, s[fn][3], src2);
            uint32_t ap[4];
            ap[0] = f2tf(odd ? x1 : x0);   // P[row g  ][key fn*8+tig  ]
            ap[1] = f2tf(odd ? x3 : x2);   // P[row g+8][key fn*8+tig  ]
            ap[2] = f2tf(odd ? y1 : y0);   // P[row g  ][key fn*8+tig+4]
            ap[3] = f2tf(odd ? y3 : y2);   // P[row g+8][key fn*8+tig+4]
#pragma unroll
            for (int dn = 0; dn < 8; dn++) {
                const uint32_t b0 = Vs[(fn * 8 + tig) * VS_STRIDE + dn * 8 + g];
                const uint32_t b1 = Vs[(fn * 8 + tig + 4) * VS_STRIDE + dn * 8 + g];
                mma_tf32(o[dn], ap, b0, b1);
            }
        }
    }

    // epilogue: normalize and write fp32 to g_y [B,T,C]
    const int b = bh >> 4;
    const int h = bh & 15;
    const float inv0 = 1.f / lrow[0];
    const float inv1 = 1.f / lrow[1];
    float* yp0 = g_y + ((size_t)(b * TLEN + row_lo)) * CDIM + h * HD;
    float* yp1 = yp0 + (size_t)8 * CDIM;
#pragma unroll
    for (int dn = 0; dn < 8; dn++) {
        float2 v0, v1;
        v0.x = o[dn][0] * inv0; v0.y = o[dn][1] * inv0;
        v1.x = o[dn][2] * inv1; v1.y = o[dn][3] * inv1;
        *(float2*)(yp0 + dn * 8 + tig * 2) = v0;
        *(float2*)(yp1 + dn * 8 + tig * 2) = v1;
    }
}

// ---------------------------------------------------------------------------
// Kernel 3: output projection (tensor core) + bias
// ---------------------------------------------------------------------------
__global__ __launch_bounds__(256, 2) void out_gemm(
    const float* __restrict__ W,      // Wo [1024,1024]
    const float* __restrict__ bias,   // [1024]
    float* __restrict__ C)            // out [4096,1024]
{
    float acc[4][4][4];
    gemm128_tf32<CDIM, CDIM>(g_y, W, acc);

    const int tid  = threadIdx.x;
    const int warp = tid >> 5;
    const int lane = tid & 31;
    const int g    = lane >> 2;
    const int tig  = lane & 3;
    const int bm   = blockIdx.y * 128;
    const int bn   = blockIdx.x * 128;
    const int wm   = (warp & 1) * 64;
    const int wn   = (warp >> 1) * 32;

#pragma unroll
    for (int fm = 0; fm < 4; fm++) {
#pragma unroll
        for (int fn = 0; fn < 4; fn++) {
            const int row0 = bm + wm + fm * 16 + g;
            const int col0 = bn + wn + fn * 8 + tig * 2;
            C[(size_t)row0 * CDIM + col0]           = acc[fm][fn][0] + bias[col0];
            C[(size_t)row0 * CDIM + col0 + 1]       = acc[fm][fn][1] + bias[col0 + 1];
            C[(size_t)(row0 + 8) * CDIM + col0]     = acc[fm][fn][2] + bias[col0];
            C[(size_t)(row0 + 8) * CDIM + col0 + 1] = acc[fm][fn][3] + bias[col0 + 1];
        }
    }
}

// ---------------------------------------------------------------------------
extern "C" void kernel_launch(void* const* d_in, const int* in_sizes, int n_in,
                              void* d_out, int out_size)
{
    const float* x    = (const float*)d_in[0];
    const float* Wqkv = (const float*)d_in[1];
    const float* bqkv = (const float*)d_in[2];
    const float* Wo   = (const float*)d_in[3];
    const float* bo   = (const float*)d_in[4];
    float* out = (float*)d_out;

    qkv_gemm<<<dim3(24, 32), 256>>>(x, Wqkv, bqkv);   // N=3072/128, M=4096/128
    attn_kernel<<<dim3(32, 32), 128>>>();             // T/64 q-tiles, B*H
    out_gemm<<<dim3(8, 32), 256>>>(Wo, bo, out);      // N=1024/128, M=4096/128
}

// round 8
// speedup vs baseline: 5.2721x; 1.0351x over previous
#include <cuda_runtime.h>
#include <cstdint>

// Problem constants
#define BSZ   2
#define TLEN  2048
#define CDIM  1024
#define NH    16
#define HD    64
#define SCALE 0.125f   // 1/sqrt(64)

// Scratch (allocation-free rule: __device__ globals)
// Q/K/V stored as tf32 bit patterns (Q pre-scaled by SCALE).
static __device__ uint32_t g_q[BSZ * NH * TLEN * HD];   // [B,H,T,D]
static __device__ uint32_t g_k[BSZ * NH * TLEN * HD];
static __device__ uint32_t g_v[BSZ * NH * TLEN * HD];
static __device__ float    g_y[BSZ * TLEN * CDIM];      // [B,T,C] attn output (fp32)

// One dynamic-smem blob shared by all kernels (per-launch sizing).
extern __shared__ unsigned char SMEMRAW[];

// ---------------------------------------------------------------------------
// helpers
// ---------------------------------------------------------------------------
__device__ __forceinline__ uint32_t f2tf(float x) {
    uint32_t t;
    asm("cvt.rna.tf32.f32 %0, %1;" : "=r"(t) : "f"(x));
    return t;
}

__device__ __forceinline__ void mma_tf32(float c[4],
                                         const uint32_t a[4],
                                         uint32_t b0, uint32_t b1) {
    asm volatile(
        "mma.sync.aligned.m16n8k8.row.col.f32.tf32.tf32.f32 "
        "{%0,%1,%2,%3},{%4,%5,%6,%7},{%8,%9},{%0,%1,%2,%3};"
        : "+f"(c[0]), "+f"(c[1]), "+f"(c[2]), "+f"(c[3])
        : "r"(a[0]), "r"(a[1]), "r"(a[2]), "r"(a[3]), "r"(b0), "r"(b1));
}

__device__ __forceinline__ void cp16(void* s, const void* g) {
    uint32_t sa = (uint32_t)__cvta_generic_to_shared(s);
    asm volatile("cp.async.cg.shared.global [%0], [%1], 16;" :: "r"(sa), "l"(g));
}
__device__ __forceinline__ void cp_commit() {
    asm volatile("cp.async.commit_group;" ::: "memory");
}
template<int n>
__device__ __forceinline__ void cp_wait() {
    asm volatile("cp.async.wait_group %0;" :: "n"(n) : "memory");
}

// ---------------------------------------------------------------------------
// tf32 GEMM core: 128x128 block tile, 8 warps (warp tile 64x32), K-chunk 16,
// 3-stage cp.async gmem->smem pipeline (fp32 in smem, cvt.rna at LDS time).
// Conflict-free fragment LDS: As stride 20 (bank=4g+tig), Ws stride 136
// (bank=8tig+g), both injective over the warp quad-groups.
// ---------------------------------------------------------------------------
#define AS_STRIDE 20
#define WS_STRIDE 136
#define GSTAGE    3
#define AS_ELEMS  (128 * AS_STRIDE)
#define WS_ELEMS  (16 * WS_STRIDE)
#define GEMM_SMEM (GSTAGE * (AS_ELEMS + WS_ELEMS) * 4)

template<int N, int K>
__device__ __forceinline__ void gemm128_tf32(const float* __restrict__ A,
                                             const float* __restrict__ W,
                                             float acc[4][4][4])
{
    float* Asm = (float*)SMEMRAW;                 // [GSTAGE][128*AS_STRIDE]
    float* Wsm = Asm + GSTAGE * AS_ELEMS;         // [GSTAGE][16*WS_STRIDE]

    const int tid  = threadIdx.x;
    const int warp = tid >> 5;
    const int lane = tid & 31;
    const int g    = lane >> 2;
    const int tig  = lane & 3;
    const int bm   = blockIdx.y * 128;
    const int bn   = blockIdx.x * 128;
    const int wm   = (warp & 1) * 64;
    const int wn   = (warp >> 1) * 32;

    const int am0 = tid >> 2;           // A row 0..63 (+64 for second)
    const int akq = (tid & 3) * 4;      // k offset
    const int wk0 = tid >> 5;           // W k-row 0..7 (+8 for second)
    const int wn4 = (tid & 31) * 4;     // n offset

    const float* Ap0 = A + (size_t)(bm + am0) * K + akq;
    const float* Ap1 = Ap0 + (size_t)64 * K;
    const float* Wp0 = W + (size_t)wk0 * N + bn + wn4;
    const float* Wp1 = Wp0 + (size_t)8 * N;

#pragma unroll
    for (int i = 0; i < 4; i++)
#pragma unroll
        for (int j = 0; j < 4; j++)
#pragma unroll
            for (int e = 0; e < 4; e++) acc[i][j][e] = 0.f;

    auto issue = [&](int c) {
        const int sl  = c % GSTAGE;
        const int off = c * 16;
        float* Ad = Asm + sl * AS_ELEMS;
        float* Wd = Wsm + sl * WS_ELEMS;
        cp16(Ad + am0 * AS_STRIDE + akq,        Ap0 + off);
        cp16(Ad + (am0 + 64) * AS_STRIDE + akq, Ap1 + off);
        cp16(Wd + wk0 * WS_STRIDE + wn4,        Wp0 + (size_t)off * N);
        cp16(Wd + (wk0 + 8) * WS_STRIDE + wn4,  Wp1 + (size_t)off * N);
        cp_commit();
    };

    issue(0);
    issue(1);

    const int NC = K / 16;
    for (int c = 0; c < NC; c++) {
        // prefetch chunk c+2 into slot (c+2)%3 (its last reader was iter c-1,
        // protected by the end-of-iter __syncthreads)
        if (c + 2 < NC) issue(c + 2);
        const int rem = NC - 1 - c;       // groups newer than c
        if (rem >= 2)      cp_wait<2>();
        else if (rem == 1) cp_wait<1>();
        else               cp_wait<0>();
        __syncthreads();

        const float* Ab = Asm + (c % GSTAGE) * AS_ELEMS;
        const float* Wb = Wsm + (c % GSTAGE) * WS_ELEMS;
#pragma unroll
        for (int ks = 0; ks < 2; ks++) {
            const int kb = ks * 8;
            uint32_t af[4][4];
#pragma unroll
            for (int fm = 0; fm < 4; fm++) {
                const int r = wm + fm * 16 + g;
                af[fm][0] = f2tf(Ab[r * AS_STRIDE + kb + tig]);
                af[fm][1] = f2tf(Ab[(r + 8) * AS_STRIDE + kb + tig]);
                af[fm][2] = f2tf(Ab[r * AS_STRIDE + kb + tig + 4]);
                af[fm][3] = f2tf(Ab[(r + 8) * AS_STRIDE + kb + tig + 4]);
            }
            uint32_t bf[4][2];
#pragma unroll
            for (int fn = 0; fn < 4; fn++) {
                const int nn = wn + fn * 8 + g;
                bf[fn][0] = f2tf(Wb[(kb + tig) * WS_STRIDE + nn]);
                bf[fn][1] = f2tf(Wb[(kb + tig + 4) * WS_STRIDE + nn]);
            }
#pragma unroll
            for (int fm = 0; fm < 4; fm++)
#pragma unroll
                for (int fn = 0; fn < 4; fn++)
                    mma_tf32(acc[fm][fn], af[fm], bf[fn][0], bf[fn][1]);
        }
        __syncthreads();
    }
}

// ---------------------------------------------------------------------------
// Kernel 1: QKV projection; epilogue scatters tf32 bits into [B,H,T,D]
// (Q pre-scaled by SCALE — exact power of two, no extra rounding error).
// ---------------------------------------------------------------------------
__global__ __launch_bounds__(256, 2) void qkv_gemm(
    const float* __restrict__ A,      // x [4096,1024]
    const float* __restrict__ W,      // Wqkv [1024,3072]
    const float* __restrict__ bias)   // [3072]
{
    float acc[4][4][4];
    gemm128_tf32<3 * CDIM, CDIM>(A, W, acc);

    const int tid  = threadIdx.x;
    const int warp = tid >> 5;
    const int lane = tid & 31;
    const int g    = lane >> 2;
    const int tig  = lane & 3;
    const int bm   = blockIdx.y * 128;
    const int bn   = blockIdx.x * 128;
    const int wm   = (warp & 1) * 64;
    const int wn   = (warp >> 1) * 32;

#pragma unroll
    for (int fm = 0; fm < 4; fm++) {
#pragma unroll
        for (int fn = 0; fn < 4; fn++) {
            const int row0 = bm + wm + fm * 16 + g;
            const int col0 = bn + wn + fn * 8 + tig * 2;
#pragma unroll
            for (int e = 0; e < 4; e++) {
                const int m = row0 + (e >> 1) * 8;
                const int n = col0 + (e & 1);
                float v = acc[fm][fn][e] + bias[n];
                const int bb    = m >> 11;
                const int t     = m & 2047;
                const int which = n >> 10;
                const int rem   = n & 1023;
                const int h     = rem >> 6;
                const int d     = rem & 63;
                if (which == 0) v *= SCALE;
                uint32_t* dst = (which == 0) ? g_q : (which == 1) ? g_k : g_v;
                dst[((bb * NH + h) * TLEN + t) * HD + d] = f2tf(v);
            }
        }
    }
}

// ---------------------------------------------------------------------------
// Kernel 2: tensor-core flash attention, inverted-causal mask (keep k >= q).
// Block = 4 warps = 64 q-rows. K/V tiles double-buffered via cp.async
// (tf32 bits, conflict-free strides). Heavy q-tiles launch first.
// ---------------------------------------------------------------------------
#define KS_STRIDE 68   // bank = 4g+tig  (injective)
#define VS_STRIDE 72   // bank = 8tig+g  (injective)
#define KS_ELEMS  (64 * KS_STRIDE)
#define VS_ELEMS  (64 * VS_STRIDE)
#define ATTN_SMEM ((2 * KS_ELEMS + 2 * VS_ELEMS) * 4)

__global__ __launch_bounds__(128, 3) void attn_kernel()
{
    uint32_t* Ksm = (uint32_t*)SMEMRAW;        // [2][64*KS_STRIDE]
    uint32_t* Vsm = Ksm + 2 * KS_ELEMS;        // [2][64*VS_STRIDE]

    const int tid  = threadIdx.x;
    const int warp = tid >> 5;
    const int lane = tid & 31;
    const int g    = lane >> 2;
    const int tig  = lane & 3;
    const int bh   = blockIdx.y;                       // b*16 + h
    const int qt   = gridDim.x - 1 - blockIdx.x;       // heavy tiles first
    const int q0   = qt * 64;
    const int nIter = (TLEN - q0) >> 6;

    const uint32_t* Qb = g_q + (size_t)bh * TLEN * HD;
    const uint32_t* Kb = g_k + (size_t)bh * TLEN * HD;
    const uint32_t* Vb = g_v + (size_t)bh * TLEN * HD;

    auto issue = [&](int it) {
        const int k0 = q0 + it * 64;
        uint32_t* Kd = Ksm + (it & 1) * KS_ELEMS;
        uint32_t* Vd = Vsm + (it & 1) * VS_ELEMS;
#pragma unroll
        for (int i = 0; i < 8; i++) {
            const int idx = tid + i * 128;     // 0..1023 uint4 slots
            const int r = idx >> 4;
            const int c = (idx & 15) << 2;
            cp16(Kd + r * KS_STRIDE + c, Kb + (size_t)(k0 + r) * HD + c);
            cp16(Vd + r * VS_STRIDE + c, Vb + (size_t)(k0 + r) * HD + c);
        }
        cp_commit();
    };

    issue(0);

    const int row_lo = q0 + warp * 16 + g;   // this thread's low q-row

    // Q fragments: register-resident for the whole KV loop
    uint32_t aQ[8][4];
#pragma unroll
    for (int kk = 0; kk < 8; kk++) {
        aQ[kk][0] = Qb[(size_t)row_lo * HD + kk * 8 + tig];
        aQ[kk][1] = Qb[(size_t)(row_lo + 8) * HD + kk * 8 + tig];
        aQ[kk][2] = Qb[(size_t)row_lo * HD + kk * 8 + tig + 4];
        aQ[kk][3] = Qb[(size_t)(row_lo + 8) * HD + kk * 8 + tig + 4];
    }

    float o[8][4];
#pragma unroll
    for (int dn = 0; dn < 8; dn++)
#pragma unroll
        for (int e = 0; e < 4; e++) o[dn][e] = 0.f;
    float mrow[2] = {-1e30f, -1e30f};
    float lrow[2] = {0.f, 0.f};

    for (int it = 0; it < nIter; it++) {
        // prefetch next tile into the other buffer (last read at iter it-1,
        // protected by the end-of-iter __syncthreads)
        if (it + 1 < nIter) { issue(it + 1); cp_wait<1>(); }
        else                cp_wait<0>();
        __syncthreads();

        const uint32_t* Ks = Ksm + (it & 1) * KS_ELEMS;
        const uint32_t* Vs = Vsm + (it & 1) * VS_ELEMS;

        // S = Q K^T  (scale pre-folded into Q)
        float s[8][4];
#pragma unroll
        for (int fn = 0; fn < 8; fn++) {
#pragma unroll
            for (int e = 0; e < 4; e++) s[fn][e] = 0.f;
#pragma unroll
            for (int kk = 0; kk < 8; kk++) {
                const uint32_t b0 = Ks[(fn * 8 + g) * KS_STRIDE + kk * 8 + tig];
                const uint32_t b1 = Ks[(fn * 8 + g) * KS_STRIDE + kk * 8 + tig + 4];
                mma_tf32(s[fn], aQ[kk], b0, b1);
            }
        }

        // diagonal tile: mask keys with (global key) < (global q row)
        if (it == 0) {
#pragma unroll
            for (int fn = 0; fn < 8; fn++)
#pragma unroll
                for (int e = 0; e < 4; e++) {
                    const int key = fn * 8 + tig * 2 + (e & 1);
                    const int qr  = warp * 16 + g + ((e >> 1) << 3);
                    if (key < qr) s[fn][e] = -1e30f;
                }
        }

        // online softmax: row max
        float rm0 = -1e30f, rm1 = -1e30f;
#pragma unroll
        for (int fn = 0; fn < 8; fn++) {
            rm0 = fmaxf(rm0, fmaxf(s[fn][0], s[fn][1]));
            rm1 = fmaxf(rm1, fmaxf(s[fn][2], s[fn][3]));
        }
        rm0 = fmaxf(rm0, __shfl_xor_sync(0xffffffffu, rm0, 1));
        rm0 = fmaxf(rm0, __shfl_xor_sync(0xffffffffu, rm0, 2));
        rm1 = fmaxf(rm1, __shfl_xor_sync(0xffffffffu, rm1, 1));
        rm1 = fmaxf(rm1, __shfl_xor_sync(0xffffffffu, rm1, 2));

        const float mn0 = fmaxf(mrow[0], rm0);
        const float mn1 = fmaxf(mrow[1], rm1);
        const float c0 = __expf(mrow[0] - mn0);
        const float c1 = __expf(mrow[1] - mn1);
        mrow[0] = mn0; mrow[1] = mn1;
        lrow[0] *= c0; lrow[1] *= c1;
#pragma unroll
        for (int dn = 0; dn < 8; dn++) {
            o[dn][0] *= c0; o[dn][1] *= c0;
            o[dn][2] *= c1; o[dn][3] *= c1;
        }

        // P = exp(S - m), row sums
        float ps0 = 0.f, ps1 = 0.f;
#pragma unroll
        for (int fn = 0; fn < 8; fn++) {
            s[fn][0] = __expf(s[fn][0] - mn0);
            s[fn][1] = __expf(s[fn][1] - mn0);
            s[fn][2] = __expf(s[fn][2] - mn1);
            s[fn][3] = __expf(s[fn][3] - mn1);
            ps0 += s[fn][0] + s[fn][1];
            ps1 += s[fn][2] + s[fn][3];
        }
        ps0 += __shfl_xor_sync(0xffffffffu, ps0, 1);
        ps0 += __shfl_xor_sync(0xffffffffu, ps0, 2);
        ps1 += __shfl_xor_sync(0xffffffffu, ps1, 1);
        ps1 += __shfl_xor_sync(0xffffffffu, ps1, 2);
        lrow[0] += ps0; lrow[1] += ps1;

        // O += P V : shfl-transpose P C-frags into A-frags, then mma
        const int src1 = (g << 2) + (tig >> 1);
        const int src2 = src1 + 2;
        const bool odd = (tig & 1) != 0;
#pragma unroll
        for (int fn = 0; fn < 8; fn++) {
            const float x0 = __shfl_sync(0xffffffffu, s[fn][0], src1);
            const float x1 = __shfl_sync(0xffffffffu, s[fn][1], src1);
            const float x2 = __shfl_sync(0xffffffffu, s[fn][2], src1);
            const float x3 = __shfl_sync(0xffffffffu, s[fn][3], src1);
            const float y0 = __shfl_sync(0xffffffffu, s[fn][0], src2);
            const float y1 = __shfl_sync(0xffffffffu, s[fn][1], src2);
            const float y2 = __shfl_sync(0xffffffffu, s[fn][2], src2);
            const float y3 = __shfl_sync(0xffffffffu, s[fn][3], src2);
            uint32_t ap[4];
            ap[0] = f2tf(odd ? x1 : x0);
            ap[1] = f2tf(odd ? x3 : x2);
            ap[2] = f2tf(odd ? y1 : y0);
            ap[3] = f2tf(odd ? y3 : y2);
#pragma unroll
            for (int dn = 0; dn < 8; dn++) {
                const uint32_t b0 = Vs[(fn * 8 + tig) * VS_STRIDE + dn * 8 + g];
                const uint32_t b1 = Vs[(fn * 8 + tig + 4) * VS_STRIDE + dn * 8 + g];
                mma_tf32(o[dn], ap, b0, b1);
            }
        }
        __syncthreads();
    }

    // epilogue: normalize and write fp32 to g_y [B,T,C]
    const int b = bh >> 4;
    const int h = bh & 15;
    const float inv0 = 1.f / lrow[0];
    const float inv1 = 1.f / lrow[1];
    float* yp0 = g_y + ((size_t)(b * TLEN + row_lo)) * CDIM + h * HD;
    float* yp1 = yp0 + (size_t)8 * CDIM;
#pragma unroll
    for (int dn = 0; dn < 8; dn++) {
        float2 v0, v1;
        v0.x = o[dn][0] * inv0; v0.y = o[dn][1] * inv0;
        v1.x = o[dn][2] * inv1; v1.y = o[dn][3] * inv1;
        *(float2*)(yp0 + dn * 8 + tig * 2) = v0;
        *(float2*)(yp1 + dn * 8 + tig * 2) = v1;
    }
}

// ---------------------------------------------------------------------------
// Kernel 3: output projection (tensor core) + bias
// ---------------------------------------------------------------------------
__global__ __launch_bounds__(256, 2) void out_gemm(
    const float* __restrict__ W,      // Wo [1024,1024]
    const float* __restrict__ bias,   // [1024]
    float* __restrict__ C)            // out [4096,1024]
{
    float acc[4][4][4];
    gemm128_tf32<CDIM, CDIM>(g_y, W, acc);

    const int tid  = threadIdx.x;
    const int warp = tid >> 5;
    const int lane = tid & 31;
    const int g    = lane >> 2;
    const int tig  = lane & 3;
    const int bm   = blockIdx.y * 128;
    const int bn   = blockIdx.x * 128;
    const int wm   = (warp & 1) * 64;
    const int wn   = (warp >> 1) * 32;

#pragma unroll
    for (int fm = 0; fm < 4; fm++) {
#pragma unroll
        for (int fn = 0; fn < 4; fn++) {
            const int row0 = bm + wm + fm * 16 + g;
            const int col0 = bn + wn + fn * 8 + tig * 2;
            C[(size_t)row0 * CDIM + col0]           = acc[fm][fn][0] + bias[col0];
            C[(size_t)row0 * CDIM + col0 + 1]       = acc[fm][fn][1] + bias[col0 + 1];
            C[(size_t)(row0 + 8) * CDIM + col0]     = acc[fm][fn][2] + bias[col0];
            C[(size_t)(row0 + 8) * CDIM + col0 + 1] = acc[fm][fn][3] + bias[col0 + 1];
        }
    }
}

// ---------------------------------------------------------------------------
extern "C" void kernel_launch(void* const* d_in, const int* in_sizes, int n_in,
                              void* d_out, int out_size)
{
    const float* x    = (const float*)d_in[0];
    const float* Wqkv = (const float*)d_in[1];
    const float* bqkv = (const float*)d_in[2];
    const float* Wo   = (const float*)d_in[3];
    const float* bo   = (const float*)d_in[4];
    float* out = (float*)d_out;

    // >48KB dynamic smem opt-in (host-side attribute set; idempotent, runs
    // only during graph capture — zero cost on replay)
    cudaFuncSetAttribute(qkv_gemm,   cudaFuncAttributeMaxDynamicSharedMemorySize, GEMM_SMEM);
    cudaFuncSetAttribute(attn_kernel,cudaFuncAttributeMaxDynamicSharedMemorySize, ATTN_SMEM);
    cudaFuncSetAttribute(out_gemm,   cudaFuncAttributeMaxDynamicSharedMemorySize, GEMM_SMEM);

    qkv_gemm<<<dim3(24, 32), 256, GEMM_SMEM>>>(x, Wqkv, bqkv);
    attn_kernel<<<dim3(32, 32), 128, ATTN_SMEM>>>();
    out_gemm<<<dim3(8, 32), 256, GEMM_SMEM>>>(Wo, bo, out);
}